// round 3
// baseline (speedup 1.0000x reference)
#include <cuda_runtime.h>
#include <cuda_bf16.h>
#include <cstdint>

// ---------------- problem constants ----------------
#define NNODES 10000
#define NEDGES 160000
#define F_IN   2000
#define HID    128

// ---------------- device scratch (no cudaMalloc allowed) ----------------
__device__ float g_h1[NNODES * 768];      // x @ W_gat1  [N,6,128]
__device__ float g_as1[NNODES * 6];
__device__ float g_ad1[NNODES * 6];
__device__ float g_x1gat[NNODES * 128];
__device__ float g_y1[NNODES * 128];      // x1_gat @ W_gcn1
__device__ float g_cat[NNODES * 192];     // [x1_gcn | x2_gcn]
__device__ float g_h2[NNODES * 512];      // x1_gcn @ W_gat2 [N,4,128]
__device__ float g_as2[NNODES * 4];
__device__ float g_ad2[NNODES * 4];
__device__ float g_x2gat[NNODES * 128];
__device__ float g_y2[NNODES * 64];       // x2_gat @ W_gcn2
__device__ float g_skip[NNODES * 64];
__device__ float g_fused[NNODES * 64];
__device__ int   g_deg[NNODES];
__device__ int   g_cursor[NNODES];
__device__ int   g_rowptr[NNODES + 1];
__device__ int   g_col[NEDGES];
__device__ float g_dinv[NNODES];

// ---------------- graph build ----------------
__global__ void zero_kernel(int n) {
    int i = blockIdx.x * blockDim.x + threadIdx.x;
    if (i < n) { g_deg[i] = 0; g_cursor[i] = 0; }
}

__global__ void deg_kernel(const int* __restrict__ ei, int E) {
    int e = blockIdx.x * blockDim.x + threadIdx.x;
    if (e < E) atomicAdd(&g_deg[ei[E + e]], 1);
}

// single-block exclusive scan (N <= 1024 * many chunks), also computes dinv
__global__ void scan_kernel(int n) {
    __shared__ int sh[1024];
    __shared__ int carry;
    int tid = threadIdx.x;
    if (tid == 0) carry = 0;
    __syncthreads();
    for (int base = 0; base < n; base += 1024) {
        int i = base + tid;
        int v = (i < n) ? g_deg[i] : 0;
        sh[tid] = v;
        __syncthreads();
        for (int off = 1; off < 1024; off <<= 1) {
            int t = (tid >= off) ? sh[tid - off] : 0;
            __syncthreads();
            sh[tid] += t;
            __syncthreads();
        }
        if (i < n) {
            g_rowptr[i] = carry + sh[tid] - v;    // exclusive
            g_dinv[i]   = rsqrtf((float)(v + 1)); // deg incl self loop
        }
        __syncthreads();
        if (tid == 0) carry += sh[1023];
        __syncthreads();
    }
    if (tid == 0) g_rowptr[n] = carry;
}

__global__ void scatter_kernel(const int* __restrict__ ei, int E) {
    int e = blockIdx.x * blockDim.x + threadIdx.x;
    if (e < E) {
        int d = ei[E + e];
        int pos = g_rowptr[d] + atomicAdd(&g_cursor[d], 1);
        g_col[pos] = ei[e];
    }
}

// ---------------- SGEMM: C[M,Ncols] = A[M,K](lda) * B[K,Ncols] ----------------
// EPI: 0 = raw store, 1 = bias + relu
template <int BM, int BN, int BK, int TM, int TN, int EPI>
__global__ __launch_bounds__((BM / TM) * (BN / TN))
void sgemm(const float* __restrict__ A, const float* __restrict__ B,
           const float* __restrict__ bias, float* __restrict__ C,
           int M, int K, int Ncols, int lda, int ldc)
{
    constexpr int THREADS = (BM / TM) * (BN / TN);
    __shared__ __align__(16) float As[BK][BM];
    __shared__ __align__(16) float Bs[BK][BN];
    int tid = threadIdx.x;
    int bx = blockIdx.x, by = blockIdx.y;
    int tx = tid % (BN / TN);
    int ty = tid / (BN / TN);
    float acc[TM][TN];
#pragma unroll
    for (int i = 0; i < TM; i++)
#pragma unroll
        for (int j = 0; j < TN; j++) acc[i][j] = 0.f;

    constexpr int A_F4 = BM * BK / 4;
    constexpr int A_ITERS = A_F4 / THREADS;
    constexpr int B_F4 = BK * BN / 4;
    constexpr int B_ITERS = B_F4 / THREADS;
    const int rowBase = by * BM;

    for (int k0 = 0; k0 < K; k0 += BK) {
#pragma unroll
        for (int it = 0; it < A_ITERS; it++) {
            int id = tid + it * THREADS;
            int r = id / (BK / 4);
            int kq = id % (BK / 4);
            int grow = rowBase + r;
            float4 v = make_float4(0.f, 0.f, 0.f, 0.f);
            if (grow < M) v = *(const float4*)(A + (size_t)grow * lda + k0 + kq * 4);
            As[kq * 4 + 0][r] = v.x;
            As[kq * 4 + 1][r] = v.y;
            As[kq * 4 + 2][r] = v.z;
            As[kq * 4 + 3][r] = v.w;
        }
#pragma unroll
        for (int it = 0; it < B_ITERS; it++) {
            int id = tid + it * THREADS;
            int kr = id / (BN / 4);
            int cq = id % (BN / 4);
            float4 v = *(const float4*)(B + (size_t)(k0 + kr) * Ncols + bx * BN + cq * 4);
            *(float4*)&Bs[kr][cq * 4] = v;
        }
        __syncthreads();
#pragma unroll
        for (int kk = 0; kk < BK; kk++) {
            float ra[TM], rb[TN];
#pragma unroll
            for (int i = 0; i < TM; i += 4) {
                float4 t = *(const float4*)&As[kk][ty * TM + i];
                ra[i] = t.x; ra[i + 1] = t.y; ra[i + 2] = t.z; ra[i + 3] = t.w;
            }
#pragma unroll
            for (int j = 0; j < TN; j += 4) {
                float4 t = *(const float4*)&Bs[kk][tx * TN + j];
                rb[j] = t.x; rb[j + 1] = t.y; rb[j + 2] = t.z; rb[j + 3] = t.w;
            }
#pragma unroll
            for (int i = 0; i < TM; i++)
#pragma unroll
                for (int j = 0; j < TN; j++) acc[i][j] += ra[i] * rb[j];
        }
        __syncthreads();
    }
#pragma unroll
    for (int i = 0; i < TM; i++) {
        int grow = rowBase + ty * TM + i;
        if (grow >= M) continue;
#pragma unroll
        for (int j = 0; j < TN; j++) {
            int gcol = bx * BN + tx * TN + j;
            float v = acc[i][j];
            if (EPI == 1) { v += bias[gcol]; v = fmaxf(v, 0.f); }
            C[(size_t)grow * ldc + gcol] = v;
        }
    }
}

// ---------------- GAT attention scalars: as[n,h]=h·a_src, ad[n,h]=h·a_dst ----------------
template <int H>
__global__ void attn_scalars(const float* __restrict__ h,
                             const float* __restrict__ a_src,
                             const float* __restrict__ a_dst,
                             float* __restrict__ as_, float* __restrict__ ad_, int n)
{
    int lane = threadIdx.x & 31;
    int i = (blockIdx.x * blockDim.x + threadIdx.x) >> 5;
    if (i >= n) return;
    const float* hr = h + (size_t)i * H * 128;
#pragma unroll
    for (int hh = 0; hh < H; hh++) {
        float s = 0.f, d = 0.f;
#pragma unroll
        for (int k = 0; k < 4; k++) {
            int c = hh * 128 + lane + 32 * k;
            float hv = hr[c];
            s += hv * a_src[c];
            d += hv * a_dst[c];
        }
        for (int off = 16; off; off >>= 1) {
            s += __shfl_xor_sync(0xFFFFFFFFu, s, off);
            d += __shfl_xor_sync(0xFFFFFFFFu, d, off);
        }
        if (lane == 0) { as_[i * H + hh] = s; ad_[i * H + hh] = d; }
    }
}

// ---------------- GAT aggregation + head-mean + bias + LayerNorm + ReLU ----------------
template <int H>
__global__ void gat_agg(const float* __restrict__ h, const float* __restrict__ as_,
                        const float* __restrict__ ad_, const float* __restrict__ bias,
                        const float* __restrict__ gamma, const float* __restrict__ beta,
                        float* __restrict__ out, int n)
{
    int lane = threadIdx.x & 31;
    int i = (blockIdx.x * blockDim.x + threadIdx.x) >> 5;
    if (i >= n) return;
    int s0 = g_rowptr[i], e0 = g_rowptr[i + 1];

    float adi[H], selfa[H], m[H];
#pragma unroll
    for (int hh = 0; hh < H; hh++) {
        adi[hh] = ad_[i * H + hh];
        float a = as_[i * H + hh] + adi[hh];
        a = a > 0.f ? a : 0.2f * a;
        selfa[hh] = a;
        m[hh] = a;
    }
    // max (lane-parallel over edges; self included by all lanes, idempotent)
    for (int j = s0 + lane; j < e0; j += 32) {
        int src = g_col[j];
#pragma unroll
        for (int hh = 0; hh < H; hh++) {
            float a = as_[src * H + hh] + adi[hh];
            a = a > 0.f ? a : 0.2f * a;
            m[hh] = fmaxf(m[hh], a);
        }
    }
#pragma unroll
    for (int hh = 0; hh < H; hh++)
        for (int off = 16; off; off >>= 1)
            m[hh] = fmaxf(m[hh], __shfl_xor_sync(0xFFFFFFFFu, m[hh], off));
    // denominator
    float den[H];
#pragma unroll
    for (int hh = 0; hh < H; hh++) den[hh] = 0.f;
    for (int j = s0 + lane; j < e0; j += 32) {
        int src = g_col[j];
#pragma unroll
        for (int hh = 0; hh < H; hh++) {
            float a = as_[src * H + hh] + adi[hh];
            a = a > 0.f ? a : 0.2f * a;
            den[hh] += __expf(a - m[hh]);
        }
    }
#pragma unroll
    for (int hh = 0; hh < H; hh++) {
        for (int off = 16; off; off >>= 1)
            den[hh] += __shfl_xor_sync(0xFFFFFFFFu, den[hh], off);
        den[hh] += __expf(selfa[hh] - m[hh]);   // self term once (uniform per lane)
    }
    // weighted message accumulation (lanes over channels)
    float acc[H * 4];
#pragma unroll
    for (int t = 0; t < H * 4; t++) acc[t] = 0.f;
    for (int j = s0; j < e0; j++) {
        int src = g_col[j];
        float w[H];
#pragma unroll
        for (int hh = 0; hh < H; hh++) {
            float a = as_[src * H + hh] + adi[hh];
            a = a > 0.f ? a : 0.2f * a;
            w[hh] = __expf(a - m[hh]);
        }
        const float* hr = h + (size_t)src * (H * 128);
#pragma unroll
        for (int t = 0; t < H * 4; t++) acc[t] += w[t >> 2] * hr[lane + 32 * t];
    }
    {   // self loop
        const float* hr = h + (size_t)i * (H * 128);
#pragma unroll
        for (int t = 0; t < H * 4; t++)
            acc[t] += __expf(selfa[t >> 2] - m[t >> 2]) * hr[lane + 32 * t];
    }
    // head-mean + bias, then LayerNorm + ReLU over 128 channels
    float rden[H];
#pragma unroll
    for (int hh = 0; hh < H; hh++) rden[hh] = 1.f / den[hh];
    float v[4], s = 0.f, sq = 0.f;
#pragma unroll
    for (int k = 0; k < 4; k++) {
        float sum = 0.f;
#pragma unroll
        for (int hh = 0; hh < H; hh++) sum += acc[hh * 4 + k] * rden[hh];
        sum = sum * (1.0f / H) + bias[lane + 32 * k];
        v[k] = sum;
        s += sum;
        sq += sum * sum;
    }
    for (int off = 16; off; off >>= 1) {
        s += __shfl_xor_sync(0xFFFFFFFFu, s, off);
        sq += __shfl_xor_sync(0xFFFFFFFFu, sq, off);
    }
    float mu = s * (1.f / 128.f);
    float var = sq * (1.f / 128.f) - mu * mu;
    float rstd = rsqrtf(var + 1e-5f);
#pragma unroll
    for (int k = 0; k < 4; k++) {
        int c = lane + 32 * k;
        float o = (v[k] - mu) * rstd * gamma[c] + beta[c];
        out[(size_t)i * 128 + c] = fmaxf(o, 0.f);
    }
}

// ---------------- GCN aggregation + bias + ReLU ----------------
template <int C>
__global__ void gcn_agg(const float* __restrict__ y, const float* __restrict__ bias,
                        float* __restrict__ out, int ldo, int coff, int n)
{
    constexpr int R = C / 32;
    int lane = threadIdx.x & 31;
    int i = (blockIdx.x * blockDim.x + threadIdx.x) >> 5;
    if (i >= n) return;
    int s0 = g_rowptr[i], e0 = g_rowptr[i + 1];
    float di = g_dinv[i];
    float acc[R];
#pragma unroll
    for (int r = 0; r < R; r++) acc[r] = 0.f;
    for (int j = s0; j < e0; j++) {
        int src = g_col[j];
        float cf = g_dinv[src] * di;
        const float* yr = y + (size_t)src * C;
#pragma unroll
        for (int r = 0; r < R; r++) acc[r] += cf * yr[lane + 32 * r];
    }
    {   // self loop
        float cf = di * di;
        const float* yr = y + (size_t)i * C;
#pragma unroll
        for (int r = 0; r < R; r++) acc[r] += cf * yr[lane + 32 * r];
    }
#pragma unroll
    for (int r = 0; r < R; r++) {
        int c = lane + 32 * r;
        out[(size_t)i * ldo + coff + c] = fmaxf(acc[r] + bias[c], 0.f);
    }
}

// ---------------- final: LN(fused+skip) -> 64->32->16->5 MLP ----------------
__global__ void final_kernel(const float* __restrict__ fused, const float* __restrict__ skipb,
                             const float* __restrict__ g3, const float* __restrict__ be3,
                             const float* __restrict__ Wc1, const float* __restrict__ bc1,
                             const float* __restrict__ Wc2, const float* __restrict__ bc2,
                             const float* __restrict__ Wc3, const float* __restrict__ bc3,
                             float* __restrict__ out, int n)
{
    int lane = threadIdx.x & 31;
    int w = threadIdx.x >> 5;
    int i = blockIdx.x * 8 + w;
    __shared__ float fsh[8][64];
    __shared__ float h1sh[8][32];
    __shared__ float h2sh[8][16];
    if (i >= n) return;
    float v0 = fused[(size_t)i * 64 + lane] + skipb[(size_t)i * 64 + lane];
    float v1 = fused[(size_t)i * 64 + 32 + lane] + skipb[(size_t)i * 64 + 32 + lane];
    float s = v0 + v1, sq = v0 * v0 + v1 * v1;
    for (int off = 16; off; off >>= 1) {
        s += __shfl_xor_sync(0xFFFFFFFFu, s, off);
        sq += __shfl_xor_sync(0xFFFFFFFFu, sq, off);
    }
    float mu = s * (1.f / 64.f);
    float var = sq * (1.f / 64.f) - mu * mu;
    float rstd = rsqrtf(var + 1e-5f);
    fsh[w][lane]      = (v0 - mu) * rstd * g3[lane] + be3[lane];
    fsh[w][lane + 32] = (v1 - mu) * rstd * g3[lane + 32] + be3[lane + 32];
    __syncwarp();
    float a = bc1[lane];
#pragma unroll 8
    for (int c = 0; c < 64; c++) a += fsh[w][c] * Wc1[c * 32 + lane];
    h1sh[w][lane] = fmaxf(a, 0.f);
    __syncwarp();
    if (lane < 16) {
        float a2 = bc2[lane];
#pragma unroll 8
        for (int c = 0; c < 32; c++) a2 += h1sh[w][c] * Wc2[c * 16 + lane];
        h2sh[w][lane] = fmaxf(a2, 0.f);
    }
    __syncwarp();
    if (lane < 5) {
        float a3 = bc3[lane];
#pragma unroll
        for (int c = 0; c < 16; c++) a3 += h2sh[w][c] * Wc3[c * 5 + lane];
        out[(size_t)i * 5 + lane] = a3;
    }
}

// ---------------- launch ----------------
static void* symaddr(const void* sym) {
    void* p = nullptr;
    cudaGetSymbolAddress(&p, sym);
    return p;
}

extern "C" void kernel_launch(void* const* d_in, const int* in_sizes, int n_in,
                              void* d_out, int out_size)
{
    const float* x      = (const float*)d_in[0];
    const int*   ei     = (const int*)  d_in[1];
    const float* W_gat1 = (const float*)d_in[2];
    const float* a_src1 = (const float*)d_in[3];
    const float* a_dst1 = (const float*)d_in[4];
    const float* b_gat1 = (const float*)d_in[5];
    const float* W_gcn1 = (const float*)d_in[6];
    const float* b_gcn1 = (const float*)d_in[7];
    const float* W_gat2 = (const float*)d_in[8];
    const float* a_src2 = (const float*)d_in[9];
    const float* a_dst2 = (const float*)d_in[10];
    const float* b_gat2 = (const float*)d_in[11];
    const float* W_gcn2 = (const float*)d_in[12];
    const float* b_gcn2 = (const float*)d_in[13];
    const float* W_skip = (const float*)d_in[14];
    const float* b_skip = (const float*)d_in[15];
    const float* W_fuse = (const float*)d_in[16];
    const float* b_fuse = (const float*)d_in[17];
    const float* W_c1   = (const float*)d_in[18];
    const float* b_c1   = (const float*)d_in[19];
    const float* W_c2   = (const float*)d_in[20];
    const float* b_c2   = (const float*)d_in[21];
    const float* W_c3   = (const float*)d_in[22];
    const float* b_c3   = (const float*)d_in[23];
    const float* g1     = (const float*)d_in[24];
    const float* be1    = (const float*)d_in[25];
    const float* g2     = (const float*)d_in[26];
    const float* be2    = (const float*)d_in[27];
    const float* g3     = (const float*)d_in[28];
    const float* be3    = (const float*)d_in[29];

    const int N = in_sizes[0] / F_IN;       // 10000
    const int E = in_sizes[1] / 2;          // 160000

    float* p_h1    = (float*)symaddr(g_h1);
    float* p_as1   = (float*)symaddr(g_as1);
    float* p_ad1   = (float*)symaddr(g_ad1);
    float* p_x1gat = (float*)symaddr(g_x1gat);
    float* p_y1    = (float*)symaddr(g_y1);
    float* p_cat   = (float*)symaddr(g_cat);
    float* p_h2    = (float*)symaddr(g_h2);
    float* p_as2   = (float*)symaddr(g_as2);
    float* p_ad2   = (float*)symaddr(g_ad2);
    float* p_x2gat = (float*)symaddr(g_x2gat);
    float* p_y2    = (float*)symaddr(g_y2);
    float* p_skip  = (float*)symaddr(g_skip);
    float* p_fused = (float*)symaddr(g_fused);

    const int warpBlocks = (N * 32 + 255) / 256;
    const dim3 blk(256);
    const int rowsY = (N + 127) / 128;

    // graph build
    zero_kernel<<<(N + 255) / 256, blk>>>(N);
    deg_kernel<<<(E + 255) / 256, blk>>>(ei, E);
    scan_kernel<<<1, 1024>>>(N);
    scatter_kernel<<<(E + 255) / 256, blk>>>(ei, E);

    // GAT1
    sgemm<128, 128, 16, 8, 8, 0><<<dim3(768 / 128, rowsY), blk>>>(x, W_gat1, nullptr, p_h1, N, F_IN, 768, F_IN, 768);
    attn_scalars<6><<<warpBlocks, blk>>>(p_h1, a_src1, a_dst1, p_as1, p_ad1, N);
    gat_agg<6><<<warpBlocks, blk>>>(p_h1, p_as1, p_ad1, b_gat1, g1, be1, p_x1gat, N);

    // GCN1 -> cat[:, 0:128]
    sgemm<128, 128, 16, 8, 8, 0><<<dim3(1, rowsY), blk>>>(p_x1gat, W_gcn1, nullptr, p_y1, N, 128, 128, 128, 128);
    gcn_agg<128><<<warpBlocks, blk>>>(p_y1, b_gcn1, p_cat, 192, 0, N);

    // GAT2 (input = x1_gcn stored in cat with stride 192)
    sgemm<128, 128, 16, 8, 8, 0><<<dim3(512 / 128, rowsY), blk>>>(p_cat, W_gat2, nullptr, p_h2, N, 128, 512, 192, 512);
    attn_scalars<4><<<warpBlocks, blk>>>(p_h2, a_src2, a_dst2, p_as2, p_ad2, N);
    gat_agg<4><<<warpBlocks, blk>>>(p_h2, p_as2, p_ad2, b_gat2, g2, be2, p_x2gat, N);

    // GCN2 -> cat[:, 128:192]
    sgemm<128, 64, 16, 8, 4, 0><<<dim3(1, rowsY), blk>>>(p_x2gat, W_gcn2, nullptr, p_y2, N, 128, 64, 128, 64);
    gcn_agg<64><<<warpBlocks, blk>>>(p_y2, b_gcn2, p_cat, 192, 128, N);

    // skip + fuse
    sgemm<128, 64, 16, 8, 4, 1><<<dim3(1, rowsY), blk>>>(x, W_skip, b_skip, p_skip, N, F_IN, 64, F_IN, 64);
    sgemm<128, 64, 16, 8, 4, 1><<<dim3(1, rowsY), blk>>>(p_cat, W_fuse, b_fuse, p_fused, N, 192, 64, 192, 64);

    // final LN + classifier
    final_kernel<<<(N + 7) / 8, blk>>>(p_fused, p_skip, g3, be3,
                                       W_c1, b_c1, W_c2, b_c2, W_c3, b_c3,
                                       (float*)d_out, N);
}

// round 4
// speedup vs baseline: 1.7306x; 1.7306x over previous
#include <cuda_runtime.h>
#include <cuda_bf16.h>
#include <cstdint>

// ---------------- problem constants ----------------
#define NNODES 10000
#define NEDGES 160000
#define F_IN   2000
#define HID    128

// ---------------- device scratch (no cudaMalloc allowed) ----------------
__device__ float g_h1[NNODES * 768];      // x @ W_gat1  [N,6,128]
__device__ float g_as1[NNODES * 6];
__device__ float g_ad1[NNODES * 6];
__device__ float g_x1gat[NNODES * 128];
__device__ float g_y1[NNODES * 128];      // x1_gat @ W_gcn1
__device__ float g_cat[NNODES * 192];     // [x1_gcn | x2_gcn]
__device__ float g_h2[NNODES * 512];      // x1_gcn @ W_gat2 [N,4,128]
__device__ float g_as2[NNODES * 4];
__device__ float g_ad2[NNODES * 4];
__device__ float g_x2gat[NNODES * 128];
__device__ float g_y2[NNODES * 64];       // x2_gat @ W_gcn2
__device__ float g_skip[NNODES * 64];
__device__ float g_fused[NNODES * 64];
__device__ int   g_deg[NNODES];
__device__ int   g_cursor[NNODES];
__device__ int   g_rowptr[NNODES + 1];
__device__ int   g_col[NEDGES];
__device__ float g_dinv[NNODES];

// ---------------- graph build ----------------
__global__ void zero_kernel(int n) {
    int i = blockIdx.x * blockDim.x + threadIdx.x;
    if (i < n) { g_deg[i] = 0; g_cursor[i] = 0; }
}

__global__ void deg_kernel(const int* __restrict__ ei, int E) {
    int e = blockIdx.x * blockDim.x + threadIdx.x;
    if (e < E) atomicAdd(&g_deg[ei[E + e]], 1);
}

// single-block exclusive scan, also computes dinv
__global__ void scan_kernel(int n) {
    __shared__ int sh[1024];
    __shared__ int carry;
    int tid = threadIdx.x;
    if (tid == 0) carry = 0;
    __syncthreads();
    for (int base = 0; base < n; base += 1024) {
        int i = base + tid;
        int v = (i < n) ? g_deg[i] : 0;
        sh[tid] = v;
        __syncthreads();
        for (int off = 1; off < 1024; off <<= 1) {
            int t = (tid >= off) ? sh[tid - off] : 0;
            __syncthreads();
            sh[tid] += t;
            __syncthreads();
        }
        if (i < n) {
            g_rowptr[i] = carry + sh[tid] - v;    // exclusive
            g_dinv[i]   = rsqrtf((float)(v + 1)); // deg incl self loop
        }
        __syncthreads();
        if (tid == 0) carry += sh[1023];
        __syncthreads();
    }
    if (tid == 0) g_rowptr[n] = carry;
}

__global__ void scatter_kernel(const int* __restrict__ ei, int E) {
    int e = blockIdx.x * blockDim.x + threadIdx.x;
    if (e < E) {
        int d = ei[E + e];
        int pos = g_rowptr[d] + atomicAdd(&g_cursor[d], 1);
        g_col[pos] = ei[e];
    }
}

// ---------------- TF32 tensor-core GEMM ----------------
// C[M,Ncols] = A[M,K](lda) @ B[K,Ncols], fp32 in/out, tf32 mma.sync.
// Block BM x BN, BK=32. Warp tile 32x64 (2 M-frags x 8 N-frags of m16n8k8).
// EPI: 0 = raw store, 1 = bias + relu
__device__ __forceinline__ uint32_t f2tf32(float x) {
    uint32_t r;
    asm("cvt.rna.tf32.f32 %0, %1;" : "=r"(r) : "f"(x));
    return r;
}

template <int BM, int BN, int BK, int EPI>
__global__ __launch_bounds__((BM / 32) * (BN / 64) * 32)
void tf32gemm(const float* __restrict__ A, const float* __restrict__ B,
              const float* __restrict__ bias, float* __restrict__ C,
              int M, int K, int Ncols, int lda, int ldc)
{
    constexpr int NWY = BM / 32;
    constexpr int NWX = BN / 64;
    constexpr int THREADS = NWY * NWX * 32;
    __shared__ float As[BK][BM + 4];
    __shared__ float Bs[BK][BN + 4];

    const int tid = threadIdx.x;
    const int wid = tid >> 5, lane = tid & 31;
    const int g = lane >> 2, tg = lane & 3;
    const int wm = (wid % NWY) * 32;
    const int wn = (wid / NWY) * 64;
    const int rowBase = blockIdx.y * BM;
    const int colBase = blockIdx.x * BN;

    float acc[2][8][4];
#pragma unroll
    for (int mf = 0; mf < 2; mf++)
#pragma unroll
        for (int nf = 0; nf < 8; nf++)
#pragma unroll
            for (int t = 0; t < 4; t++) acc[mf][nf][t] = 0.f;

    constexpr int A_ITERS = BM * BK / 4 / THREADS;
    constexpr int B_ITERS = BK * BN / 4 / THREADS;

    for (int k0 = 0; k0 < K; k0 += BK) {
#pragma unroll
        for (int it = 0; it < A_ITERS; it++) {
            int id = tid + it * THREADS;
            int r = id / (BK / 4);
            int kq = id % (BK / 4);
            int grow = rowBase + r;
            int gk = k0 + kq * 4;
            float4 v = make_float4(0.f, 0.f, 0.f, 0.f);
            if (grow < M && gk < K)
                v = *(const float4*)(A + (size_t)grow * lda + gk);
            As[kq * 4 + 0][r] = __uint_as_float(f2tf32(v.x));
            As[kq * 4 + 1][r] = __uint_as_float(f2tf32(v.y));
            As[kq * 4 + 2][r] = __uint_as_float(f2tf32(v.z));
            As[kq * 4 + 3][r] = __uint_as_float(f2tf32(v.w));
        }
#pragma unroll
        for (int it = 0; it < B_ITERS; it++) {
            int id = tid + it * THREADS;
            int kr = id / (BN / 4);
            int cq = id % (BN / 4);
            float4 v = make_float4(0.f, 0.f, 0.f, 0.f);
            if (k0 + kr < K)
                v = *(const float4*)(B + (size_t)(k0 + kr) * Ncols + colBase + cq * 4);
            float4 o;
            o.x = __uint_as_float(f2tf32(v.x));
            o.y = __uint_as_float(f2tf32(v.y));
            o.z = __uint_as_float(f2tf32(v.z));
            o.w = __uint_as_float(f2tf32(v.w));
            *(float4*)&Bs[kr][cq * 4] = o;
        }
        __syncthreads();
#pragma unroll
        for (int ks = 0; ks < BK; ks += 8) {
            uint32_t a[2][4], b[8][2];
#pragma unroll
            for (int mf = 0; mf < 2; mf++) {
                int rb = wm + mf * 16 + g;
                a[mf][0] = __float_as_uint(As[ks + tg][rb]);
                a[mf][1] = __float_as_uint(As[ks + tg][rb + 8]);
                a[mf][2] = __float_as_uint(As[ks + tg + 4][rb]);
                a[mf][3] = __float_as_uint(As[ks + tg + 4][rb + 8]);
            }
#pragma unroll
            for (int nf = 0; nf < 8; nf++) {
                int cb = wn + nf * 8 + g;
                b[nf][0] = __float_as_uint(Bs[ks + tg][cb]);
                b[nf][1] = __float_as_uint(Bs[ks + tg + 4][cb]);
            }
#pragma unroll
            for (int mf = 0; mf < 2; mf++)
#pragma unroll
                for (int nf = 0; nf < 8; nf++) {
                    asm volatile(
                        "mma.sync.aligned.m16n8k8.row.col.f32.tf32.tf32.f32 "
                        "{%0,%1,%2,%3}, {%4,%5,%6,%7}, {%8,%9}, {%0,%1,%2,%3};"
                        : "+f"(acc[mf][nf][0]), "+f"(acc[mf][nf][1]),
                          "+f"(acc[mf][nf][2]), "+f"(acc[mf][nf][3])
                        : "r"(a[mf][0]), "r"(a[mf][1]), "r"(a[mf][2]), "r"(a[mf][3]),
                          "r"(b[nf][0]), "r"(b[nf][1]));
                }
        }
        __syncthreads();
    }

    // epilogue
#pragma unroll
    for (int mf = 0; mf < 2; mf++) {
#pragma unroll
        for (int nf = 0; nf < 8; nf++) {
            int r0 = rowBase + wm + mf * 16 + g;
            int r1 = r0 + 8;
            int c = colBase + wn + nf * 8 + tg * 2;
            float v0 = acc[mf][nf][0], v1 = acc[mf][nf][1];
            float v2 = acc[mf][nf][2], v3 = acc[mf][nf][3];
            if (EPI == 1) {
                float bz0 = bias[c], bz1 = bias[c + 1];
                v0 = fmaxf(v0 + bz0, 0.f); v1 = fmaxf(v1 + bz1, 0.f);
                v2 = fmaxf(v2 + bz0, 0.f); v3 = fmaxf(v3 + bz1, 0.f);
            }
            if (r0 < M) *(float2*)(C + (size_t)r0 * ldc + c) = make_float2(v0, v1);
            if (r1 < M) *(float2*)(C + (size_t)r1 * ldc + c) = make_float2(v2, v3);
        }
    }
}

// ---------------- GAT attention scalars: as[n,h]=h·a_src, ad[n,h]=h·a_dst ----------------
template <int H>
__global__ void attn_scalars(const float* __restrict__ h,
                             const float* __restrict__ a_src,
                             const float* __restrict__ a_dst,
                             float* __restrict__ as_, float* __restrict__ ad_, int n)
{
    int lane = threadIdx.x & 31;
    int i = (blockIdx.x * blockDim.x + threadIdx.x) >> 5;
    if (i >= n) return;
    const float* hr = h + (size_t)i * H * 128;
#pragma unroll
    for (int hh = 0; hh < H; hh++) {
        float s = 0.f, d = 0.f;
#pragma unroll
        for (int k = 0; k < 4; k++) {
            int c = hh * 128 + lane + 32 * k;
            float hv = hr[c];
            s += hv * a_src[c];
            d += hv * a_dst[c];
        }
        for (int off = 16; off; off >>= 1) {
            s += __shfl_xor_sync(0xFFFFFFFFu, s, off);
            d += __shfl_xor_sync(0xFFFFFFFFu, d, off);
        }
        if (lane == 0) { as_[i * H + hh] = s; ad_[i * H + hh] = d; }
    }
}

// ---------------- GAT aggregation + head-mean + bias + LayerNorm + ReLU ----------------
template <int H>
__global__ void gat_agg(const float* __restrict__ h, const float* __restrict__ as_,
                        const float* __restrict__ ad_, const float* __restrict__ bias,
                        const float* __restrict__ gamma, const float* __restrict__ beta,
                        float* __restrict__ out, int n)
{
    int lane = threadIdx.x & 31;
    int i = (blockIdx.x * blockDim.x + threadIdx.x) >> 5;
    if (i >= n) return;
    int s0 = g_rowptr[i], e0 = g_rowptr[i + 1];

    float adi[H], selfa[H], m[H];
#pragma unroll
    for (int hh = 0; hh < H; hh++) {
        adi[hh] = ad_[i * H + hh];
        float a = as_[i * H + hh] + adi[hh];
        a = a > 0.f ? a : 0.2f * a;
        selfa[hh] = a;
        m[hh] = a;
    }
    for (int j = s0 + lane; j < e0; j += 32) {
        int src = g_col[j];
#pragma unroll
        for (int hh = 0; hh < H; hh++) {
            float a = as_[src * H + hh] + adi[hh];
            a = a > 0.f ? a : 0.2f * a;
            m[hh] = fmaxf(m[hh], a);
        }
    }
#pragma unroll
    for (int hh = 0; hh < H; hh++)
        for (int off = 16; off; off >>= 1)
            m[hh] = fmaxf(m[hh], __shfl_xor_sync(0xFFFFFFFFu, m[hh], off));
    float den[H];
#pragma unroll
    for (int hh = 0; hh < H; hh++) den[hh] = 0.f;
    for (int j = s0 + lane; j < e0; j += 32) {
        int src = g_col[j];
#pragma unroll
        for (int hh = 0; hh < H; hh++) {
            float a = as_[src * H + hh] + adi[hh];
            a = a > 0.f ? a : 0.2f * a;
            den[hh] += __expf(a - m[hh]);
        }
    }
#pragma unroll
    for (int hh = 0; hh < H; hh++) {
        for (int off = 16; off; off >>= 1)
            den[hh] += __shfl_xor_sync(0xFFFFFFFFu, den[hh], off);
        den[hh] += __expf(selfa[hh] - m[hh]);
    }
    float acc[H * 4];
#pragma unroll
    for (int t = 0; t < H * 4; t++) acc[t] = 0.f;
    for (int j = s0; j < e0; j++) {
        int src = g_col[j];
        float w[H];
#pragma unroll
        for (int hh = 0; hh < H; hh++) {
            float a = as_[src * H + hh] + adi[hh];
            a = a > 0.f ? a : 0.2f * a;
            w[hh] = __expf(a - m[hh]);
        }
        const float* hr = h + (size_t)src * (H * 128);
#pragma unroll
        for (int t = 0; t < H * 4; t++) acc[t] += w[t >> 2] * hr[lane + 32 * t];
    }
    {
        const float* hr = h + (size_t)i * (H * 128);
#pragma unroll
        for (int t = 0; t < H * 4; t++)
            acc[t] += __expf(selfa[t >> 2] - m[t >> 2]) * hr[lane + 32 * t];
    }
    float rden[H];
#pragma unroll
    for (int hh = 0; hh < H; hh++) rden[hh] = 1.f / den[hh];
    float v[4], s = 0.f, sq = 0.f;
#pragma unroll
    for (int k = 0; k < 4; k++) {
        float sum = 0.f;
#pragma unroll
        for (int hh = 0; hh < H; hh++) sum += acc[hh * 4 + k] * rden[hh];
        sum = sum * (1.0f / H) + bias[lane + 32 * k];
        v[k] = sum;
        s += sum;
        sq += sum * sum;
    }
    for (int off = 16; off; off >>= 1) {
        s += __shfl_xor_sync(0xFFFFFFFFu, s, off);
        sq += __shfl_xor_sync(0xFFFFFFFFu, sq, off);
    }
    float mu = s * (1.f / 128.f);
    float var = sq * (1.f / 128.f) - mu * mu;
    float rstd = rsqrtf(var + 1e-5f);
#pragma unroll
    for (int k = 0; k < 4; k++) {
        int c = lane + 32 * k;
        float o = (v[k] - mu) * rstd * gamma[c] + beta[c];
        out[(size_t)i * 128 + c] = fmaxf(o, 0.f);
    }
}

// ---------------- GCN aggregation + bias + ReLU ----------------
template <int C>
__global__ void gcn_agg(const float* __restrict__ y, const float* __restrict__ bias,
                        float* __restrict__ out, int ldo, int coff, int n)
{
    constexpr int R = C / 32;
    int lane = threadIdx.x & 31;
    int i = (blockIdx.x * blockDim.x + threadIdx.x) >> 5;
    if (i >= n) return;
    int s0 = g_rowptr[i], e0 = g_rowptr[i + 1];
    float di = g_dinv[i];
    float acc[R];
#pragma unroll
    for (int r = 0; r < R; r++) acc[r] = 0.f;
    for (int j = s0; j < e0; j++) {
        int src = g_col[j];
        float cf = g_dinv[src] * di;
        const float* yr = y + (size_t)src * C;
#pragma unroll
        for (int r = 0; r < R; r++) acc[r] += cf * yr[lane + 32 * r];
    }
    {
        float cf = di * di;
        const float* yr = y + (size_t)i * C;
#pragma unroll
        for (int r = 0; r < R; r++) acc[r] += cf * yr[lane + 32 * r];
    }
#pragma unroll
    for (int r = 0; r < R; r++) {
        int c = lane + 32 * r;
        out[(size_t)i * ldo + coff + c] = fmaxf(acc[r] + bias[c], 0.f);
    }
}

// ---------------- final: LN(fused+skip) -> 64->32->16->5 MLP ----------------
__global__ void final_kernel(const float* __restrict__ fused, const float* __restrict__ skipb,
                             const float* __restrict__ g3, const float* __restrict__ be3,
                             const float* __restrict__ Wc1, const float* __restrict__ bc1,
                             const float* __restrict__ Wc2, const float* __restrict__ bc2,
                             const float* __restrict__ Wc3, const float* __restrict__ bc3,
                             float* __restrict__ out, int n)
{
    int lane = threadIdx.x & 31;
    int w = threadIdx.x >> 5;
    int i = blockIdx.x * 8 + w;
    __shared__ float fsh[8][64];
    __shared__ float h1sh[8][32];
    __shared__ float h2sh[8][16];
    if (i >= n) return;
    float v0 = fused[(size_t)i * 64 + lane] + skipb[(size_t)i * 64 + lane];
    float v1 = fused[(size_t)i * 64 + 32 + lane] + skipb[(size_t)i * 64 + 32 + lane];
    float s = v0 + v1, sq = v0 * v0 + v1 * v1;
    for (int off = 16; off; off >>= 1) {
        s += __shfl_xor_sync(0xFFFFFFFFu, s, off);
        sq += __shfl_xor_sync(0xFFFFFFFFu, sq, off);
    }
    float mu = s * (1.f / 64.f);
    float var = sq * (1.f / 64.f) - mu * mu;
    float rstd = rsqrtf(var + 1e-5f);
    fsh[w][lane]      = (v0 - mu) * rstd * g3[lane] + be3[lane];
    fsh[w][lane + 32] = (v1 - mu) * rstd * g3[lane + 32] + be3[lane + 32];
    __syncwarp();
    float a = bc1[lane];
#pragma unroll 8
    for (int c = 0; c < 64; c++) a += fsh[w][c] * Wc1[c * 32 + lane];
    h1sh[w][lane] = fmaxf(a, 0.f);
    __syncwarp();
    if (lane < 16) {
        float a2 = bc2[lane];
#pragma unroll 8
        for (int c = 0; c < 32; c++) a2 += h1sh[w][c] * Wc2[c * 16 + lane];
        h2sh[w][lane] = fmaxf(a2, 0.f);
    }
    __syncwarp();
    if (lane < 5) {
        float a3 = bc3[lane];
#pragma unroll
        for (int c = 0; c < 16; c++) a3 += h2sh[w][c] * Wc3[c * 5 + lane];
        out[(size_t)i * 5 + lane] = a3;
    }
}

// ---------------- launch ----------------
static void* symaddr(const void* sym) {
    void* p = nullptr;
    cudaGetSymbolAddress(&p, sym);
    return p;
}

extern "C" void kernel_launch(void* const* d_in, const int* in_sizes, int n_in,
                              void* d_out, int out_size)
{
    const float* x      = (const float*)d_in[0];
    const int*   ei     = (const int*)  d_in[1];
    const float* W_gat1 = (const float*)d_in[2];
    const float* a_src1 = (const float*)d_in[3];
    const float* a_dst1 = (const float*)d_in[4];
    const float* b_gat1 = (const float*)d_in[5];
    const float* W_gcn1 = (const float*)d_in[6];
    const float* b_gcn1 = (const float*)d_in[7];
    const float* W_gat2 = (const float*)d_in[8];
    const float* a_src2 = (const float*)d_in[9];
    const float* a_dst2 = (const float*)d_in[10];
    const float* b_gat2 = (const float*)d_in[11];
    const float* W_gcn2 = (const float*)d_in[12];
    const float* b_gcn2 = (const float*)d_in[13];
    const float* W_skip = (const float*)d_in[14];
    const float* b_skip = (const float*)d_in[15];
    const float* W_fuse = (const float*)d_in[16];
    const float* b_fuse = (const float*)d_in[17];
    const float* W_c1   = (const float*)d_in[18];
    const float* b_c1   = (const float*)d_in[19];
    const float* W_c2   = (const float*)d_in[20];
    const float* b_c2   = (const float*)d_in[21];
    const float* W_c3   = (const float*)d_in[22];
    const float* b_c3   = (const float*)d_in[23];
    const float* g1     = (const float*)d_in[24];
    const float* be1    = (const float*)d_in[25];
    const float* g2     = (const float*)d_in[26];
    const float* be2    = (const float*)d_in[27];
    const float* g3     = (const float*)d_in[28];
    const float* be3    = (const float*)d_in[29];

    const int N = in_sizes[0] / F_IN;       // 10000
    const int E = in_sizes[1] / 2;          // 160000

    float* p_h1    = (float*)symaddr(g_h1);
    float* p_as1   = (float*)symaddr(g_as1);
    float* p_ad1   = (float*)symaddr(g_ad1);
    float* p_x1gat = (float*)symaddr(g_x1gat);
    float* p_y1    = (float*)symaddr(g_y1);
    float* p_cat   = (float*)symaddr(g_cat);
    float* p_h2    = (float*)symaddr(g_h2);
    float* p_as2   = (float*)symaddr(g_as2);
    float* p_ad2   = (float*)symaddr(g_ad2);
    float* p_x2gat = (float*)symaddr(g_x2gat);
    float* p_y2    = (float*)symaddr(g_y2);
    float* p_skip  = (float*)symaddr(g_skip);
    float* p_fused = (float*)symaddr(g_fused);

    const int warpBlocks = (N * 32 + 255) / 256;
    const dim3 blk(256);
    const int rowsY = (N + 127) / 128;

    // graph build
    zero_kernel<<<(N + 255) / 256, blk>>>(N);
    deg_kernel<<<(E + 255) / 256, blk>>>(ei, E);
    scan_kernel<<<1, 1024>>>(N);
    scatter_kernel<<<(E + 255) / 256, blk>>>(ei, E);

    // GAT1: x @ W_gat1 -> [N, 768]  (tensor cores)
    tf32gemm<128, 128, 32, 0><<<dim3(768 / 128, rowsY), 256>>>(x, W_gat1, nullptr, p_h1, N, F_IN, 768, F_IN, 768);
    attn_scalars<6><<<warpBlocks, blk>>>(p_h1, a_src1, a_dst1, p_as1, p_ad1, N);
    gat_agg<6><<<warpBlocks, blk>>>(p_h1, p_as1, p_ad1, b_gat1, g1, be1, p_x1gat, N);

    // GCN1 -> cat[:, 0:128]
    tf32gemm<128, 128, 32, 0><<<dim3(1, rowsY), 256>>>(p_x1gat, W_gcn1, nullptr, p_y1, N, 128, 128, 128, 128);
    gcn_agg<128><<<warpBlocks, blk>>>(p_y1, b_gcn1, p_cat, 192, 0, N);

    // GAT2 (input = x1_gcn stored in cat with stride 192)
    tf32gemm<128, 128, 32, 0><<<dim3(512 / 128, rowsY), 256>>>(p_cat, W_gat2, nullptr, p_h2, N, 128, 512, 192, 512);
    attn_scalars<4><<<warpBlocks, blk>>>(p_h2, a_src2, a_dst2, p_as2, p_ad2, N);
    gat_agg<4><<<warpBlocks, blk>>>(p_h2, p_as2, p_ad2, b_gat2, g2, be2, p_x2gat, N);

    // GCN2 -> cat[:, 128:192]
    tf32gemm<128, 64, 32, 0><<<dim3(1, rowsY), 128>>>(p_x2gat, W_gcn2, nullptr, p_y2, N, 128, 64, 128, 64);
    gcn_agg<64><<<warpBlocks, blk>>>(p_y2, b_gcn2, p_cat, 192, 128, N);

    // skip + fuse
    tf32gemm<128, 64, 32, 1><<<dim3(1, rowsY), 128>>>(x, W_skip, b_skip, p_skip, N, F_IN, 64, F_IN, 64);
    tf32gemm<128, 64, 32, 1><<<dim3(1, rowsY), 128>>>(p_cat, W_fuse, b_fuse, p_fused, N, 192, 64, 192, 64);

    // final LN + classifier
    final_kernel<<<(N + 7) / 8, blk>>>(p_fused, p_skip, g3, be3,
                                       W_c1, b_c1, W_c2, b_c2, W_c3, b_c3,
                                       (float*)d_out, N);
}

// round 6
// speedup vs baseline: 2.6528x; 1.5329x over previous
#include <cuda_runtime.h>
#include <cuda_bf16.h>
#include <cstdint>

// ---------------- problem constants ----------------
#define NNODES 10000
#define NEDGES 160000
#define F_IN   2000
#define HID    128

// ---------------- device scratch (no cudaMalloc allowed) ----------------
__device__ float g_xr[NNODES * F_IN];     // tf32-rounded x (80MB)
__device__ float g_wr[2000 * 768 + 128 * 128 + 128 * 512 + 128 * 64 + 2000 * 64 + 192 * 64];
__device__ float g_h1[NNODES * 768];      // x @ W_gat1  [N,6,128]
__device__ float g_as1[NNODES * 6];
__device__ float g_ad1[NNODES * 6];
__device__ float g_x1gat[NNODES * 128];
__device__ float g_y1[NNODES * 128];      // x1_gat @ W_gcn1
__device__ float g_cat[NNODES * 192];     // [x1_gcn | x2_gcn] (tf32-rounded)
__device__ float g_h2[NNODES * 512];      // x1_gcn @ W_gat2 [N,4,128]
__device__ float g_as2[NNODES * 4];
__device__ float g_ad2[NNODES * 4];
__device__ float g_x2gat[NNODES * 128];
__device__ float g_y2[NNODES * 64];       // x2_gat @ W_gcn2
__device__ float g_skip[NNODES * 64];
__device__ float g_fused[NNODES * 64];
__device__ int   g_deg[NNODES];
__device__ int   g_cursor[NNODES];
__device__ int   g_rowptr[NNODES + 1];
__device__ int   g_col[NEDGES];
__device__ float g_dinv[NNODES];

// weight offsets inside g_wr
#define WOFF_GAT1 0
#define WOFF_GCN1 (WOFF_GAT1 + 2000 * 768)
#define WOFF_GAT2 (WOFF_GCN1 + 128 * 128)
#define WOFF_GCN2 (WOFF_GAT2 + 128 * 512)
#define WOFF_SKIP (WOFF_GCN2 + 128 * 64)
#define WOFF_FUSE (WOFF_SKIP + 2000 * 64)

__device__ __forceinline__ float rnd_tf32(float x) {
    uint32_t r;
    asm("cvt.rna.tf32.f32 %0, %1;" : "=r"(r) : "f"(x));
    return __uint_as_float(r);
}

// ---------------- tf32 pre-rounding ----------------
__global__ void round_tf32_kernel(const float* __restrict__ in, float* __restrict__ out, int n4) {
    int i = blockIdx.x * blockDim.x + threadIdx.x;
    if (i < n4) {
        float4 v = ((const float4*)in)[i];
        v.x = rnd_tf32(v.x); v.y = rnd_tf32(v.y);
        v.z = rnd_tf32(v.z); v.w = rnd_tf32(v.w);
        ((float4*)out)[i] = v;
    }
}

// ---------------- graph build ----------------
__global__ void zero_kernel(int n) {
    int i = blockIdx.x * blockDim.x + threadIdx.x;
    if (i < n) { g_deg[i] = 0; g_cursor[i] = 0; }
}

__global__ void deg_kernel(const int* __restrict__ ei, int E) {
    int e = blockIdx.x * blockDim.x + threadIdx.x;
    if (e < E) atomicAdd(&g_deg[ei[E + e]], 1);
}

__global__ void scan_kernel(int n) {
    __shared__ int sh[1024];
    __shared__ int carry;
    int tid = threadIdx.x;
    if (tid == 0) carry = 0;
    __syncthreads();
    for (int base = 0; base < n; base += 1024) {
        int i = base + tid;
        int v = (i < n) ? g_deg[i] : 0;
        sh[tid] = v;
        __syncthreads();
        for (int off = 1; off < 1024; off <<= 1) {
            int t = (tid >= off) ? sh[tid - off] : 0;
            __syncthreads();
            sh[tid] += t;
            __syncthreads();
        }
        if (i < n) {
            g_rowptr[i] = carry + sh[tid] - v;
            g_dinv[i]   = rsqrtf((float)(v + 1));
        }
        __syncthreads();
        if (tid == 0) carry += sh[1023];
        __syncthreads();
    }
    if (tid == 0) g_rowptr[n] = carry;
}

__global__ void scatter_kernel(const int* __restrict__ ei, int E) {
    int e = blockIdx.x * blockDim.x + threadIdx.x;
    if (e < E) {
        int d = ei[E + e];
        int pos = g_rowptr[d] + atomicAdd(&g_cursor[d], 1);
        g_col[pos] = ei[e];
    }
}

// ---------------- pipelined TF32 tensor-core GEMM ----------------
// C[M,Ncols] = A[M,K](lda) @ B[K,Ncols]. A,B must be tf32-pre-rounded fp32.
// Double-buffered cp.async. Warp tile WM x 64 (MF = WM/16 m-frags of m16n8k8).
// EPI: 0 = raw store, 1 = bias + relu.
template <int BM, int BN, int BK, int WM, int EPI>
__global__ __launch_bounds__((BM / WM) * (BN / 64) * 32)
void tf32gemm_pipe(const float* __restrict__ A, const float* __restrict__ B,
                   const float* __restrict__ bias, float* __restrict__ C,
                   int M, int K, int Ncols, int lda, int ldc)
{
    constexpr int NWY = BM / WM;
    constexpr int NWX = BN / 64;
    constexpr int THREADS = NWY * NWX * 32;
    constexpr int MF = WM / 16;
    constexpr int ASTR = BK + 4;   // 36: a-frag banks 4g+tg, conflict-free
    constexpr int BSTR = BN + 8;   // b-frag banks 8tg+g, conflict-free
    constexpr int A_ITERS = BM * BK / 4 / THREADS;
    constexpr int B_ITERS = BK * BN / 4 / THREADS;

    extern __shared__ float smem[];
    float* As = smem;                       // [2][BM][ASTR]
    float* Bs = smem + 2 * BM * ASTR;       // [2][BK][BSTR]

    const int tid = threadIdx.x;
    const int wid = tid >> 5, lane = tid & 31;
    const int g = lane >> 2, tg = lane & 3;
    const int wm = (wid % NWY) * WM;
    const int wn = (wid / NWY) * 64;
    const int rowBase = blockIdx.y * BM;
    const int colBase = blockIdx.x * BN;

    float acc[MF][8][4];
#pragma unroll
    for (int mf = 0; mf < MF; mf++)
#pragma unroll
        for (int nf = 0; nf < 8; nf++)
#pragma unroll
            for (int t = 0; t < 4; t++) acc[mf][nf][t] = 0.f;

    auto load_tiles = [&](int stage, int k0) {
        float* Asb = As + stage * BM * ASTR;
        float* Bsb = Bs + stage * BK * BSTR;
#pragma unroll
        for (int it = 0; it < A_ITERS; it++) {
            int id = tid + it * THREADS;
            int r = id / (BK / 4);
            int kq = id % (BK / 4);
            int grow = rowBase + r, gk = k0 + kq * 4;
            int sz = (grow < M && gk < K) ? 16 : 0;
            const float* src = A + (size_t)min(grow, M - 1) * lda + min(gk, K - 4);
            uint32_t dst = (uint32_t)__cvta_generic_to_shared(Asb + r * ASTR + kq * 4);
            asm volatile("cp.async.cg.shared.global [%0], [%1], 16, %2;"
                         :: "r"(dst), "l"(src), "r"(sz));
        }
#pragma unroll
        for (int it = 0; it < B_ITERS; it++) {
            int id = tid + it * THREADS;
            int kr = id / (BN / 4);
            int cq = id % (BN / 4);
            int gk = k0 + kr;
            int sz = (gk < K) ? 16 : 0;
            const float* src = B + (size_t)min(gk, K - 1) * Ncols + colBase + cq * 4;
            uint32_t dst = (uint32_t)__cvta_generic_to_shared(Bsb + kr * BSTR + cq * 4);
            asm volatile("cp.async.cg.shared.global [%0], [%1], 16, %2;"
                         :: "r"(dst), "l"(src), "r"(sz));
        }
        asm volatile("cp.async.commit_group;");
    };

    const int iters = (K + BK - 1) / BK;
    load_tiles(0, 0);

    for (int it = 0; it < iters; it++) {
        if (it + 1 < iters) {
            load_tiles((it + 1) & 1, (it + 1) * BK);
            asm volatile("cp.async.wait_group 1;");
        } else {
            asm volatile("cp.async.wait_group 0;");
        }
        __syncthreads();

        const float* Asb = As + (it & 1) * BM * ASTR;
        const float* Bsb = Bs + (it & 1) * BK * BSTR;
#pragma unroll
        for (int ks = 0; ks < BK; ks += 8) {
            uint32_t a[MF][4], b[8][2];
#pragma unroll
            for (int mf = 0; mf < MF; mf++) {
                int rb = wm + mf * 16 + g;
                a[mf][0] = __float_as_uint(Asb[rb * ASTR + ks + tg]);
                a[mf][1] = __float_as_uint(Asb[(rb + 8) * ASTR + ks + tg]);
                a[mf][2] = __float_as_uint(Asb[rb * ASTR + ks + tg + 4]);
                a[mf][3] = __float_as_uint(Asb[(rb + 8) * ASTR + ks + tg + 4]);
            }
#pragma unroll
            for (int nf = 0; nf < 8; nf++) {
                int cb = wn + nf * 8 + g;
                b[nf][0] = __float_as_uint(Bsb[(ks + tg) * BSTR + cb]);
                b[nf][1] = __float_as_uint(Bsb[(ks + tg + 4) * BSTR + cb]);
            }
#pragma unroll
            for (int mf = 0; mf < MF; mf++)
#pragma unroll
                for (int nf = 0; nf < 8; nf++) {
                    asm volatile(
                        "mma.sync.aligned.m16n8k8.row.col.f32.tf32.tf32.f32 "
                        "{%0,%1,%2,%3}, {%4,%5,%6,%7}, {%8,%9}, {%0,%1,%2,%3};"
                        : "+f"(acc[mf][nf][0]), "+f"(acc[mf][nf][1]),
                          "+f"(acc[mf][nf][2]), "+f"(acc[mf][nf][3])
                        : "r"(a[mf][0]), "r"(a[mf][1]), "r"(a[mf][2]), "r"(a[mf][3]),
                          "r"(b[nf][0]), "r"(b[nf][1]));
                }
        }
        __syncthreads();
    }

    // epilogue
#pragma unroll
    for (int mf = 0; mf < MF; mf++) {
#pragma unroll
        for (int nf = 0; nf < 8; nf++) {
            int r0 = rowBase + wm + mf * 16 + g;
            int r1 = r0 + 8;
            int c = colBase + wn + nf * 8 + tg * 2;
            float v0 = acc[mf][nf][0], v1 = acc[mf][nf][1];
            float v2 = acc[mf][nf][2], v3 = acc[mf][nf][3];
            if (EPI == 1) {
                float bz0 = bias[c], bz1 = bias[c + 1];
                v0 = fmaxf(v0 + bz0, 0.f); v1 = fmaxf(v1 + bz1, 0.f);
                v2 = fmaxf(v2 + bz0, 0.f); v3 = fmaxf(v3 + bz1, 0.f);
            }
            if (r0 < M) *(float2*)(C + (size_t)r0 * ldc + c) = make_float2(v0, v1);
            if (r1 < M) *(float2*)(C + (size_t)r1 * ldc + c) = make_float2(v2, v3);
        }
    }
}

// ---------------- GAT attention scalars ----------------
template <int H>
__global__ void attn_scalars(const float* __restrict__ h,
                             const float* __restrict__ a_src,
                             const float* __restrict__ a_dst,
                             float* __restrict__ as_, float* __restrict__ ad_, int n)
{
    int lane = threadIdx.x & 31;
    int i = (blockIdx.x * blockDim.x + threadIdx.x) >> 5;
    if (i >= n) return;
    const float* hr = h + (size_t)i * H * 128;
#pragma unroll
    for (int hh = 0; hh < H; hh++) {
        float s = 0.f, d = 0.f;
#pragma unroll
        for (int k = 0; k < 4; k++) {
            int c = hh * 128 + lane + 32 * k;
            float hv = hr[c];
            s += hv * a_src[c];
            d += hv * a_dst[c];
        }
        for (int off = 16; off; off >>= 1) {
            s += __shfl_xor_sync(0xFFFFFFFFu, s, off);
            d += __shfl_xor_sync(0xFFFFFFFFu, d, off);
        }
        if (lane == 0) { as_[i * H + hh] = s; ad_[i * H + hh] = d; }
    }
}

// ---------------- GAT aggregation + head-mean + bias + LayerNorm + ReLU ----------------
// Output is tf32-rounded (it feeds a GEMM only).
template <int H>
__global__ void gat_agg(const float* __restrict__ h, const float* __restrict__ as_,
                        const float* __restrict__ ad_, const float* __restrict__ bias,
                        const float* __restrict__ gamma, const float* __restrict__ beta,
                        float* __restrict__ out, int n)
{
    int lane = threadIdx.x & 31;
    int i = (blockIdx.x * blockDim.x + threadIdx.x) >> 5;
    if (i >= n) return;
    int s0 = g_rowptr[i], e0 = g_rowptr[i + 1];

    float adi[H], selfa[H], m[H];
#pragma unroll
    for (int hh = 0; hh < H; hh++) {
        adi[hh] = ad_[i * H + hh];
        float a = as_[i * H + hh] + adi[hh];
        a = a > 0.f ? a : 0.2f * a;
        selfa[hh] = a;
        m[hh] = a;
    }
    for (int j = s0 + lane; j < e0; j += 32) {
        int src = g_col[j];
#pragma unroll
        for (int hh = 0; hh < H; hh++) {
            float a = as_[src * H + hh] + adi[hh];
            a = a > 0.f ? a : 0.2f * a;
            m[hh] = fmaxf(m[hh], a);
        }
    }
#pragma unroll
    for (int hh = 0; hh < H; hh++)
        for (int off = 16; off; off >>= 1)
            m[hh] = fmaxf(m[hh], __shfl_xor_sync(0xFFFFFFFFu, m[hh], off));
    float den[H];
#pragma unroll
    for (int hh = 0; hh < H; hh++) den[hh] = 0.f;
    for (int j = s0 + lane; j < e0; j += 32) {
        int src = g_col[j];
#pragma unroll
        for (int hh = 0; hh < H; hh++) {
            float a = as_[src * H + hh] + adi[hh];
            a = a > 0.f ? a : 0.2f * a;
            den[hh] += __expf(a - m[hh]);
        }
    }
#pragma unroll
    for (int hh = 0; hh < H; hh++) {
        for (int off = 16; off; off >>= 1)
            den[hh] += __shfl_xor_sync(0xFFFFFFFFu, den[hh], off);
        den[hh] += __expf(selfa[hh] - m[hh]);
    }
    float acc[H * 4];
#pragma unroll
    for (int t = 0; t < H * 4; t++) acc[t] = 0.f;
    for (int j = s0; j < e0; j++) {
        int src = g_col[j];
        float w[H];
#pragma unroll
        for (int hh = 0; hh < H; hh++) {
            float a = as_[src * H + hh] + adi[hh];
            a = a > 0.f ? a : 0.2f * a;
            w[hh] = __expf(a - m[hh]);
        }
        const float* hr = h + (size_t)src * (H * 128);
#pragma unroll
        for (int t = 0; t < H * 4; t++) acc[t] += w[t >> 2] * hr[lane + 32 * t];
    }
    {
        const float* hr = h + (size_t)i * (H * 128);
#pragma unroll
        for (int t = 0; t < H * 4; t++)
            acc[t] += __expf(selfa[t >> 2] - m[t >> 2]) * hr[lane + 32 * t];
    }
    float rden[H];
#pragma unroll
    for (int hh = 0; hh < H; hh++) rden[hh] = 1.f / den[hh];
    float v[4], s = 0.f, sq = 0.f;
#pragma unroll
    for (int k = 0; k < 4; k++) {
        float sum = 0.f;
#pragma unroll
        for (int hh = 0; hh < H; hh++) sum += acc[hh * 4 + k] * rden[hh];
        sum = sum * (1.0f / H) + bias[lane + 32 * k];
        v[k] = sum;
        s += sum;
        sq += sum * sum;
    }
    for (int off = 16; off; off >>= 1) {
        s += __shfl_xor_sync(0xFFFFFFFFu, s, off);
        sq += __shfl_xor_sync(0xFFFFFFFFu, sq, off);
    }
    float mu = s * (1.f / 128.f);
    float var = sq * (1.f / 128.f) - mu * mu;
    float rstd = rsqrtf(var + 1e-5f);
#pragma unroll
    for (int k = 0; k < 4; k++) {
        int c = lane + 32 * k;
        float o = (v[k] - mu) * rstd * gamma[c] + beta[c];
        out[(size_t)i * 128 + c] = rnd_tf32(fmaxf(o, 0.f));
    }
}

// ---------------- GCN aggregation + bias + ReLU (tf32-rounded output) ----------------
template <int C>
__global__ void gcn_agg(const float* __restrict__ y, const float* __restrict__ bias,
                        float* __restrict__ out, int ldo, int coff, int n)
{
    constexpr int R = C / 32;
    int lane = threadIdx.x & 31;
    int i = (blockIdx.x * blockDim.x + threadIdx.x) >> 5;
    if (i >= n) return;
    int s0 = g_rowptr[i], e0 = g_rowptr[i + 1];
    float di = g_dinv[i];
    float acc[R];
#pragma unroll
    for (int r = 0; r < R; r++) acc[r] = 0.f;
    for (int j = s0; j < e0; j++) {
        int src = g_col[j];
        float cf = g_dinv[src] * di;
        const float* yr = y + (size_t)src * C;
#pragma unroll
        for (int r = 0; r < R; r++) acc[r] += cf * yr[lane + 32 * r];
    }
    {
        float cf = di * di;
        const float* yr = y + (size_t)i * C;
#pragma unroll
        for (int r = 0; r < R; r++) acc[r] += cf * yr[lane + 32 * r];
    }
#pragma unroll
    for (int r = 0; r < R; r++) {
        int c = lane + 32 * r;
        out[(size_t)i * ldo + coff + c] = rnd_tf32(fmaxf(acc[r] + bias[c], 0.f));
    }
}

// ---------------- final: LN(fused+skip) -> 64->32->16->5 MLP ----------------
__global__ void final_kernel(const float* __restrict__ fused, const float* __restrict__ skipb,
                             const float* __restrict__ g3, const float* __restrict__ be3,
                             const float* __restrict__ Wc1, const float* __restrict__ bc1,
                             const float* __restrict__ Wc2, const float* __restrict__ bc2,
                             const float* __restrict__ Wc3, const float* __restrict__ bc3,
                             float* __restrict__ out, int n)
{
    int lane = threadIdx.x & 31;
    int w = threadIdx.x >> 5;
    int i = blockIdx.x * 8 + w;
    __shared__ float fsh[8][64];
    __shared__ float h1sh[8][32];
    __shared__ float h2sh[8][16];
    if (i >= n) return;
    float v0 = fused[(size_t)i * 64 + lane] + skipb[(size_t)i * 64 + lane];
    float v1 = fused[(size_t)i * 64 + 32 + lane] + skipb[(size_t)i * 64 + 32 + lane];
    float s = v0 + v1, sq = v0 * v0 + v1 * v1;
    for (int off = 16; off; off >>= 1) {
        s += __shfl_xor_sync(0xFFFFFFFFu, s, off);
        sq += __shfl_xor_sync(0xFFFFFFFFu, sq, off);
    }
    float mu = s * (1.f / 64.f);
    float var = sq * (1.f / 64.f) - mu * mu;
    float rstd = rsqrtf(var + 1e-5f);
    fsh[w][lane]      = (v0 - mu) * rstd * g3[lane] + be3[lane];
    fsh[w][lane + 32] = (v1 - mu) * rstd * g3[lane + 32] + be3[lane + 32];
    __syncwarp();
    float a = bc1[lane];
#pragma unroll 8
    for (int c = 0; c < 64; c++) a += fsh[w][c] * Wc1[c * 32 + lane];
    h1sh[w][lane] = fmaxf(a, 0.f);
    __syncwarp();
    if (lane < 16) {
        float a2 = bc2[lane];
#pragma unroll 8
        for (int c = 0; c < 32; c++) a2 += h1sh[w][c] * Wc2[c * 16 + lane];
        h2sh[w][lane] = fmaxf(a2, 0.f);
    }
    __syncwarp();
    if (lane < 5) {
        float a3 = bc3[lane];
#pragma unroll
        for (int c = 0; c < 16; c++) a3 += h2sh[w][c] * Wc3[c * 5 + lane];
        out[(size_t)i * 5 + lane] = a3;
    }
}

// ---------------- launch ----------------
static void* symaddr(const void* sym) {
    void* p = nullptr;
    cudaGetSymbolAddress(&p, sym);
    return p;
}

extern "C" void kernel_launch(void* const* d_in, const int* in_sizes, int n_in,
                              void* d_out, int out_size)
{
    const float* x      = (const float*)d_in[0];
    const int*   ei     = (const int*)  d_in[1];
    const float* W_gat1 = (const float*)d_in[2];
    const float* a_src1 = (const float*)d_in[3];
    const float* a_dst1 = (const float*)d_in[4];
    const float* b_gat1 = (const float*)d_in[5];
    const float* W_gcn1 = (const float*)d_in[6];
    const float* b_gcn1 = (const float*)d_in[7];
    const float* W_gat2 = (const float*)d_in[8];
    const float* a_src2 = (const float*)d_in[9];
    const float* a_dst2 = (const float*)d_in[10];
    const float* b_gat2 = (const float*)d_in[11];
    const float* W_gcn2 = (const float*)d_in[12];
    const float* b_gcn2 = (const float*)d_in[13];
    const float* W_skip = (const float*)d_in[14];
    const float* b_skip = (const float*)d_in[15];
    const float* W_fuse = (const float*)d_in[16];
    const float* b_fuse = (const float*)d_in[17];
    const float* W_c1   = (const float*)d_in[18];
    const float* b_c1   = (const float*)d_in[19];
    const float* W_c2   = (const float*)d_in[20];
    const float* b_c2   = (const float*)d_in[21];
    const float* W_c3   = (const float*)d_in[22];
    const float* b_c3   = (const float*)d_in[23];
    const float* g1     = (const float*)d_in[24];
    const float* be1    = (const float*)d_in[25];
    const float* g2     = (const float*)d_in[26];
    const float* be2    = (const float*)d_in[27];
    const float* g3     = (const float*)d_in[28];
    const float* be3    = (const float*)d_in[29];

    const int N = in_sizes[0] / F_IN;       // 10000
    const int E = in_sizes[1] / 2;          // 160000

    float* p_xr    = (float*)symaddr(g_xr);
    float* p_wr    = (float*)symaddr(g_wr);
    float* p_h1    = (float*)symaddr(g_h1);
    float* p_as1   = (float*)symaddr(g_as1);
    float* p_ad1   = (float*)symaddr(g_ad1);
    float* p_x1gat = (float*)symaddr(g_x1gat);
    float* p_y1    = (float*)symaddr(g_y1);
    float* p_cat   = (float*)symaddr(g_cat);
    float* p_h2    = (float*)symaddr(g_h2);
    float* p_as2   = (float*)symaddr(g_as2);
    float* p_ad2   = (float*)symaddr(g_ad2);
    float* p_x2gat = (float*)symaddr(g_x2gat);
    float* p_y2    = (float*)symaddr(g_y2);
    float* p_skip  = (float*)symaddr(g_skip);
    float* p_fused = (float*)symaddr(g_fused);

    const int warpBlocks = (N * 32 + 255) / 256;
    const dim3 blk(256);
    const int rowsY = (N + 127) / 128;      // 79

    constexpr int SMEM_BIG   = (2 * 128 * 36 + 2 * 32 * 136) * 4;  // 71680
    constexpr int SMEM_SMALL = (2 * 128 * 36 + 2 * 32 * 72) * 4;   // 55296

    cudaFuncSetAttribute((const void*)tf32gemm_pipe<128, 128, 32, 64, 0>,
                         cudaFuncAttributeMaxDynamicSharedMemorySize, SMEM_BIG);
    cudaFuncSetAttribute((const void*)tf32gemm_pipe<128, 64, 32, 32, 0>,
                         cudaFuncAttributeMaxDynamicSharedMemorySize, SMEM_SMALL);
    cudaFuncSetAttribute((const void*)tf32gemm_pipe<128, 64, 32, 32, 1>,
                         cudaFuncAttributeMaxDynamicSharedMemorySize, SMEM_SMALL);

    // tf32 pre-rounding: x and all GEMM weights
    {
        int n4 = N * F_IN / 4;
        round_tf32_kernel<<<(n4 + 255) / 256, blk>>>(x, p_xr, n4);
        round_tf32_kernel<<<(2000 * 768 / 4 + 255) / 256, blk>>>(W_gat1, p_wr + WOFF_GAT1, 2000 * 768 / 4);
        round_tf32_kernel<<<(128 * 128 / 4 + 255) / 256, blk>>>(W_gcn1, p_wr + WOFF_GCN1, 128 * 128 / 4);
        round_tf32_kernel<<<(128 * 512 / 4 + 255) / 256, blk>>>(W_gat2, p_wr + WOFF_GAT2, 128 * 512 / 4);
        round_tf32_kernel<<<(128 * 64 / 4 + 255) / 256, blk>>>(W_gcn2, p_wr + WOFF_GCN2, 128 * 64 / 4);
        round_tf32_kernel<<<(2000 * 64 / 4 + 255) / 256, blk>>>(W_skip, p_wr + WOFF_SKIP, 2000 * 64 / 4);
        round_tf32_kernel<<<(192 * 64 / 4 + 255) / 256, blk>>>(W_fuse, p_wr + WOFF_FUSE, 192 * 64 / 4);
    }

    // graph build
    zero_kernel<<<(N + 255) / 256, blk>>>(N);
    deg_kernel<<<(E + 255) / 256, blk>>>(ei, E);
    scan_kernel<<<1, 1024>>>(N);
    scatter_kernel<<<(E + 255) / 256, blk>>>(ei, E);

    // GAT1: xr @ W_gat1 -> [N, 768]
    tf32gemm_pipe<128, 128, 32, 64, 0><<<dim3(6, rowsY), 128, SMEM_BIG>>>(
        p_xr, p_wr + WOFF_GAT1, nullptr, p_h1, N, F_IN, 768, F_IN, 768);
    attn_scalars<6><<<warpBlocks, blk>>>(p_h1, a_src1, a_dst1, p_as1, p_ad1, N);
    gat_agg<6><<<warpBlocks, blk>>>(p_h1, p_as1, p_ad1, b_gat1, g1, be1, p_x1gat, N);

    // GCN1 -> cat[:, 0:128]
    tf32gemm_pipe<128, 128, 32, 64, 0><<<dim3(1, rowsY), 128, SMEM_BIG>>>(
        p_x1gat, p_wr + WOFF_GCN1, nullptr, p_y1, N, 128, 128, 128, 128);
    gcn_agg<128><<<warpBlocks, blk>>>(p_y1, b_gcn1, p_cat, 192, 0, N);

    // GAT2 (input = x1_gcn stored in cat with stride 192)
    tf32gemm_pipe<128, 128, 32, 64, 0><<<dim3(4, rowsY), 128, SMEM_BIG>>>(
        p_cat, p_wr + WOFF_GAT2, nullptr, p_h2, N, 128, 512, 192, 512);
    attn_scalars<4><<<warpBlocks, blk>>>(p_h2, a_src2, a_dst2, p_as2, p_ad2, N);
    gat_agg<4><<<warpBlocks, blk>>>(p_h2, p_as2, p_ad2, b_gat2, g2, be2, p_x2gat, N);

    // GCN2 -> cat[:, 128:192]
    tf32gemm_pipe<128, 64, 32, 32, 0><<<dim3(1, rowsY), 128, SMEM_SMALL>>>(
        p_x2gat, p_wr + WOFF_GCN2, nullptr, p_y2, N, 128, 64, 128, 64);
    gcn_agg<64><<<warpBlocks, blk>>>(p_y2, b_gcn2, p_cat, 192, 128, N);

    // skip + fuse
    tf32gemm_pipe<128, 64, 32, 32, 1><<<dim3(1, rowsY), 128, SMEM_SMALL>>>(
        p_xr, p_wr + WOFF_SKIP, b_skip, p_skip, N, F_IN, 64, F_IN, 64);
    tf32gemm_pipe<128, 64, 32, 32, 1><<<dim3(1, rowsY), 128, SMEM_SMALL>>>(
        p_cat, p_wr + WOFF_FUSE, b_fuse, p_fused, N, 192, 64, 192, 64);

    // final LN + classifier
    final_kernel<<<(N + 7) / 8, blk>>>(p_fused, p_skip, g3, be3,
                                       W_c1, b_c1, W_c2, b_c2, W_c3, b_c3,
                                       (float*)d_out, N);
}